// round 2
// baseline (speedup 1.0000x reference)
#include <cuda_runtime.h>
#include <cstdint>

// GridCellRouter: H=W=4096, N=16,777,216 cells, 16 iterations.
//   accum = scatter_add(accum, flow_idx, cur)
//   cur   = accum - cur
// Output: accum after 16 iterations.
//
// Round 2: L2 eviction-priority management.
//   accum -> evict_last (pinned resident: atomics + sequential reads all L2)
//   idx   -> evict_first (pure one-shot stream)
//   cur   -> default (lives in the remaining normal-priority L2 between phases)

#define N_CELLS (4096 * 4096)
#define ITERS 16

__device__ float g_cur[N_CELLS];   // 64 MB scratch (allocation-free)

// ---- L2 policy helpers -----------------------------------------------------

// red.global.add.f32 with L2::evict_last policy (keeps accum resident)
__device__ __forceinline__ void red_add_el(float* p, float v) {
    asm volatile(
        "{ .reg .b64 pol;\n"
        "  createpolicy.fractional.L2::evict_last.b64 pol, 1.0;\n"
        "  red.global.L2::cache_hint.add.f32 [%0], %1, pol; }"
        :: "l"(p), "f"(v) : "memory");
}

// v4 float load with L2::evict_last policy (accum sequential read in update)
__device__ __forceinline__ float4 ld_el_f4(const float4* p) {
    float4 v;
    asm volatile(
        "{ .reg .b64 pol;\n"
        "  createpolicy.fractional.L2::evict_last.b64 pol, 1.0;\n"
        "  ld.global.L2::cache_hint.v4.f32 {%0,%1,%2,%3}, [%4], pol; }"
        : "=f"(v.x), "=f"(v.y), "=f"(v.z), "=f"(v.w) : "l"(p));
    return v;
}

// evict-first (streaming) int4 load for the index array
__device__ __forceinline__ int4 ldcs_i4(const int4* p) {
    int4 v;
    asm volatile("ld.global.cs.v4.b32 {%0,%1,%2,%3}, [%4];"
                 : "=r"(v.x), "=r"(v.y), "=r"(v.z), "=r"(v.w) : "l"(p));
    return v;
}

// ---- kernels ---------------------------------------------------------------

// accum = runoff (d_out is poisoned; must be initialized). evict_last store
// would be ideal but a plain store is fine: first scatter re-pins lines anyway.
__global__ void init_kernel(const float4* __restrict__ runoff,
                            float4* __restrict__ accum, int n4) {
    int i = blockIdx.x * blockDim.x + threadIdx.x;
    if (i < n4) accum[i] = runoff[i];
}

// Phase 1: atomicAdd(accum[idx[i]], cur[i]).
__global__ void scatter_kernel(const float* __restrict__ cur,
                               const int* __restrict__ idx,
                               float* __restrict__ accum, int n4) {
    int t = blockIdx.x * blockDim.x + threadIdx.x;
    if (t >= n4) return;
    // cur: default policy -> stays in normal-priority L2 for the update phase
    float4 c = reinterpret_cast<const float4*>(cur)[t];
    int4 d = ldcs_i4(reinterpret_cast<const int4*>(idx) + t);
    red_add_el(accum + d.x, c.x);
    red_add_el(accum + d.y, c.y);
    red_add_el(accum + d.z, c.z);
    red_add_el(accum + d.w, c.w);
}

// Phase 2: cur_out[i] = accum[i] - cur_in[i].
__global__ void update_kernel(const float4* __restrict__ accum,
                              const float* __restrict__ cur_in,
                              float* __restrict__ cur_out, int n4) {
    int t = blockIdx.x * blockDim.x + threadIdx.x;
    if (t >= n4) return;
    float4 a = ld_el_f4(accum + t);                              // L2 hit (pinned)
    float4 c = reinterpret_cast<const float4*>(cur_in)[t];       // L2 hit (hot from scatter)
    float4 o;
    o.x = a.x - c.x; o.y = a.y - c.y; o.z = a.z - c.z; o.w = a.w - c.w;
    reinterpret_cast<float4*>(cur_out)[t] = o;                   // default -> resident for next scatter
}

extern "C" void kernel_launch(void* const* d_in, const int* in_sizes, int n_in,
                              void* d_out, int out_size) {
    const float* runoff = (const float*)d_in[0];
    const int* flow_idx = (const int*)d_in[1];
    float* accum = (float*)d_out;

    float* cur = nullptr;
    cudaGetSymbolAddress((void**)&cur, g_cur);

    const int n4 = N_CELLS / 4;                       // 4,194,304
    const int threads = 256;
    const int blocks = (n4 + threads - 1) / threads;  // 16,384

    init_kernel<<<blocks, threads>>>((const float4*)runoff, (float4*)accum, n4);

    const float* cur_src = runoff;                    // iteration 1 reads runoff directly
    for (int it = 0; it < ITERS; ++it) {
        scatter_kernel<<<blocks, threads>>>(cur_src, flow_idx, accum, n4);
        update_kernel<<<blocks, threads>>>((const float4*)accum, cur_src, cur, n4);
        cur_src = cur;
    }
}